// round 12
// baseline (speedup 1.0000x reference)
#include <cuda_runtime.h>
#include <cuda_fp16.h>
#include <cstdint>

#define L_SEQ 8192
#define D_IN  512
#define O_OUT 1024
#define BATCH 8

// Scratch (device-global: allocation-free per harness rules)
__device__ __half g_fb[(size_t)BATCH * O_OUT * L_SEQ];   // 128 MB (fp16)
__device__ __half g_ah[(size_t)O_OUT * D_IN];            // 1 MB   (Wn in fp16)

// ---------------------------------------------------------------------------
// Kernel 1: normalize W rows -> fp16
// ---------------------------------------------------------------------------
__global__ void normalize_w_kernel(const float* __restrict__ W) {
    int o = blockIdx.x;          // 1024 rows
    int tid = threadIdx.x;       // 128 threads
    const float* row = W + (size_t)o * D_IN;
    float s = 0.f;
    for (int i = tid; i < D_IN; i += 128) { float w = row[i]; s = fmaf(w, w, s); }
    #pragma unroll
    for (int off = 16; off; off >>= 1) s += __shfl_xor_sync(0xffffffffu, s, off);
    __shared__ float red[4];
    if ((tid & 31) == 0) red[tid >> 5] = s;
    __syncthreads();
    float tot = red[0] + red[1] + red[2] + red[3];
    // Wn = W / (EPS + ||W||/sqrt(fan)) / sqrt(fan) = W / (EPS*sqrt(fan) + ||W||)
    float inv = 1.0f / (1e-4f * sqrtf((float)D_IN) + sqrtf(tot));
    for (int i = tid; i < D_IN; i += 128)
        g_ah[(size_t)o * D_IN + i] = __float2half_rn(row[i] * inv);
}

// ---------------------------------------------------------------------------
// Kernel 2: GEMM fb = Wn @ x, fp16 HMMA, K=512, fused f32->fp16 B conversion.
// CTA tile 128x128, 256 threads (8 warps 2x4, warp tile 64x32), 2 CTAs/SM.
// Single-sync double buffer: during iter it, compute reads buf[it&1] while
// ALL writes (B STS for it+1, A cp.async for it+1) go to buf[(it+1)&1].
// One __syncthreads per iteration (R11 had two + mid-iter ordering).
// ---------------------------------------------------------------------------
#define GBM 128
#define GBN 128
#define GBK 32
#define ITERS (D_IN / GBK)        // 16

#define LDA 40                    // halves per A smem row (32 + pad 8)
#define LDB 136                   // halves per B smem row (128 + pad 8)
#define A_SZ (GBM * LDA * 2)      // 10240
#define B_SZ (GBK * LDB * 2)      // 8704
#define STAGE_SZ (A_SZ + B_SZ)    // 18944
#define SMEM_TOTAL (2 * STAGE_SZ) // 37888

__device__ __forceinline__ uint32_t smem_u32(const void* p) {
    uint32_t a;
    asm("{ .reg .u64 t; cvta.to.shared.u64 t, %1; cvt.u32.u64 %0, t; }" : "=r"(a) : "l"(p));
    return a;
}
__device__ __forceinline__ void cp16(uint32_t dst, const void* src) {
    asm volatile("cp.async.cg.shared.global [%0], [%1], 16;" :: "r"(dst), "l"(src));
}
__device__ __forceinline__ void ldsm_x4(uint32_t* r, uint32_t addr) {
    asm volatile("ldmatrix.sync.aligned.m8n8.x4.shared.b16 {%0,%1,%2,%3}, [%4];"
        : "=r"(r[0]), "=r"(r[1]), "=r"(r[2]), "=r"(r[3]) : "r"(addr));
}
__device__ __forceinline__ void ldsm_x4_t(uint32_t* r, uint32_t addr) {
    asm volatile("ldmatrix.sync.aligned.m8n8.x4.trans.shared.b16 {%0,%1,%2,%3}, [%4];"
        : "=r"(r[0]), "=r"(r[1]), "=r"(r[2]), "=r"(r[3]) : "r"(addr));
}
__device__ __forceinline__ void mma_f16(float* c, const uint32_t* a, uint32_t b0, uint32_t b1) {
    asm volatile("mma.sync.aligned.m16n8k16.row.col.f32.f16.f16.f32 "
        "{%0,%1,%2,%3}, {%4,%5,%6,%7}, {%8,%9}, {%0,%1,%2,%3};"
        : "+f"(c[0]), "+f"(c[1]), "+f"(c[2]), "+f"(c[3])
        : "r"(a[0]), "r"(a[1]), "r"(a[2]), "r"(a[3]), "r"(b0), "r"(b1));
}

// A stage: 128 rows x 32 halves = 512 x 16B chunks, 2 per thread
__device__ __forceinline__ void load_stage_A(uint32_t sb, int m0, int ld, int tid) {
    const uint32_t st = sb + (uint32_t)(ld & 1) * STAGE_SZ;
    #pragma unroll
    for (int j = 0; j < 2; j++) {
        int idx = tid + j * 256;
        int row = idx >> 2, ch = idx & 3;
        cp16(st + row * (LDA * 2) + ch * 16,
             g_ah + (size_t)(m0 + row) * D_IN + ld * GBK + ch * 8);
    }
}

__global__ void __launch_bounds__(256, 2) gemm_f16_kernel(const float* __restrict__ x) {
    extern __shared__ char smem[];
    const uint32_t sb = smem_u32(smem);

    const int tid  = threadIdx.x;
    const int lane = tid & 31;
    const int warp = tid >> 5;
    const int wm = warp >> 2;               // 0..1  (64-row slab)
    const int wn = warp & 3;                // 0..3  (32-col slab)
    const int m0 = blockIdx.x * GBM;        // M fastest -> x stripe L2 reuse
    const int n0 = blockIdx.y * GBN;
    const int b  = blockIdx.z;
    const float* xb = x + (size_t)b * D_IN * L_SEQ;

    // B load mapping: 32 k-rows x 128 f32 = 1024 x 16B chunks, 4 per thread
    int brow[4], bch[4];
    #pragma unroll
    for (int j = 0; j < 4; j++) {
        int idx = tid + j * 256;
        brow[j] = idx >> 5;
        bch[j]  = idx & 31;
    }

    float acc[4][4][4];
    #pragma unroll
    for (int mt = 0; mt < 4; mt++)
        #pragma unroll
        for (int nn = 0; nn < 4; nn++)
            #pragma unroll
            for (int i = 0; i < 4; i++) acc[mt][nn][i] = 0.f;

    // STS B(regs) -> stage buffer (ld & 1)
    auto sts_B = [&](const float4* vr, int ld) {
        char* bp = smem + (ld & 1) * STAGE_SZ + A_SZ;
        #pragma unroll
        for (int j = 0; j < 4; j++) {
            float4 v = vr[j];
            __half2 h0 = __floats2half2_rn(v.x, v.y);
            __half2 h1 = __floats2half2_rn(v.z, v.w);
            *(uint2*)(bp + brow[j] * (LDB * 2) + bch[j] * 8)
                = make_uint2(*(uint32_t*)&h0, *(uint32_t*)&h1);
        }
    };

    // ---- prologue: stage 0 fully resident, B(1) in regs ----
    float4 bReg[4];
    #pragma unroll
    for (int j = 0; j < 4; j++)
        bReg[j] = *(const float4*)(xb + (size_t)brow[j] * L_SEQ + n0 + bch[j] * 4);
    sts_B(bReg, 0);
    load_stage_A(sb, m0, 0, tid);
    asm volatile("cp.async.commit_group;");
    #pragma unroll
    for (int j = 0; j < 4; j++)
        bReg[j] = *(const float4*)(xb + (size_t)(GBK + brow[j]) * L_SEQ + n0 + bch[j] * 4);
    asm volatile("cp.async.wait_group 0;");
    __syncthreads();

    #pragma unroll 1
    for (int it = 0; it < ITERS; ++it) {
        const uint32_t st = sb + (uint32_t)(it & 1) * STAGE_SZ;

        // ---- write-ahead into the OTHER buffer (no conflict with compute) ----
        if (it + 1 < ITERS) {
            sts_B(bReg, it + 1);                 // B(it+1) regs -> nxt buffer
            load_stage_A(sb, m0, it + 1, tid);   // A(it+1) cp.async -> nxt buffer
        }
        asm volatile("cp.async.commit_group;");  // fixed group count
        if (it + 2 < ITERS) {                    // B(it+2) LDG -> regs
            const int k2 = (it + 2) * GBK;
            #pragma unroll
            for (int j = 0; j < 4; j++)
                bReg[j] = *(const float4*)(xb + (size_t)(k2 + brow[j]) * L_SEQ + n0 + bch[j] * 4);
        }

        // ---- compute(it) from current buffer ----
        #pragma unroll
        for (int kk = 0; kk < 2; kk++) {
            uint32_t af[4][4];
            #pragma unroll
            for (int mt = 0; mt < 4; mt++) {
                int row = wm * 64 + mt * 16 + (lane & 15);
                int col = kk * 16 + (lane >> 4) * 8;
                ldsm_x4(af[mt], st + (row * LDA + col) * 2);
            }
            uint32_t bf[2][4];
            #pragma unroll
            for (int ng = 0; ng < 2; ng++) {
                int krow = kk * 16 + (lane & 15);
                int col  = wn * 32 + ng * 16 + (lane >> 4) * 8;
                ldsm_x4_t(bf[ng], st + A_SZ + (krow * LDB + col) * 2);
            }
            #pragma unroll
            for (int mt = 0; mt < 4; mt++)
                #pragma unroll
                for (int ng = 0; ng < 2; ng++) {
                    mma_f16(acc[mt][2 * ng + 0], af[mt], bf[ng][0], bf[ng][1]);
                    mma_f16(acc[mt][2 * ng + 1], af[mt], bf[ng][2], bf[ng][3]);
                }
        }

        // ---- publish nxt buffer: single barrier per iteration ----
        asm volatile("cp.async.wait_group 0;");  // A(it+1) resident
        __syncthreads();
    }

    // epilogue -> g_fb (fp16)
    __half* fbb = g_fb + (size_t)b * O_OUT * L_SEQ;
    #pragma unroll
    for (int mt = 0; mt < 4; mt++) {
        int row = m0 + wm * 64 + mt * 16 + (lane >> 2);
        #pragma unroll
        for (int nn = 0; nn < 4; nn++) {
            int col = n0 + wn * 32 + nn * 8 + (lane & 3) * 2;
            __half2 v01 = __floats2half2_rn(acc[mt][nn][0], acc[mt][nn][1]);
            __half2 v23 = __floats2half2_rn(acc[mt][nn][2], acc[mt][nn][3]);
            *(__half2*)&fbb[(size_t)row * L_SEQ + col]       = v01;
            *(__half2*)&fbb[(size_t)(row + 8) * L_SEQ + col] = v23;
        }
    }
}

// ---------------------------------------------------------------------------
// Kernel 3: parallel linear-recurrence scan (fwd + bwd), H_t = a*H_{t-1} + v
// ---------------------------------------------------------------------------
__device__ __forceinline__ void gate(float h, float g, float& a, float& v) {
    float en = __expf(-fabsf(g));               // e^{-|g|} (fast path, ~2 ulp)
    float q  = rsqrtf(fmaf(en, en, 1.0f));      // 1/sqrt(1+en^2)
    float eq = en * q;
    bool pos = (g >= 0.f);
    a = pos ? eq : q;           // sigma(-g)*sqrt(1+sech g)
    v = (pos ? q : eq) * h;     // sigma(g)*sqrt(1+sech g)*h
}

__device__ __forceinline__ float4 load_h4(const __half* p, int rev) {
    uint2 u = *(const uint2*)p;
    __half2* hh = (__half2*)&u;
    float2 p0 = __half22float2(hh[0]);
    float2 p1 = __half22float2(hh[1]);
    if (!rev) return make_float4(p0.x, p0.y, p1.x, p1.y);
    return make_float4(p1.y, p1.x, p0.y, p0.x);
}

__global__ void __launch_bounds__(256) scan_kernel(float* __restrict__ out) {
    const int sid = blockIdx.x;            // 0..4095
    const int b   = sid >> 9;
    const int rem = sid & 511;
    const int dir = rem >> 8;              // 0 fwd, 1 bwd
    const int ch  = rem & 255;

    const __half* hp = g_fb + ((size_t)b * O_OUT + (size_t)dir * 512 + ch) * L_SEQ;
    const __half* gp = hp + (size_t)256 * L_SEQ;
    float* op = out + ((size_t)b * 512 + (size_t)dir * 256 + ch) * L_SEQ;

    const int tid = threadIdx.x;
    const int lane = tid & 31;
    const int warp = tid >> 5;

    __shared__ float totA[8], totV[8];
    float carryH = 0.f;

    #pragma unroll 1
    for (int s = 0; s < L_SEQ / 1024; ++s) {
        const int base = s * 1024 + tid * 4;
        float4 h4, g4;
        if (dir == 0) {
            h4 = load_h4(hp + base, 0);
            g4 = load_h4(gp + base, 0);
        } else {
            int gi = L_SEQ - 4 - base;
            h4 = load_h4(hp + gi, 1);
            g4 = load_h4(gp + gi, 1);
        }

        float a[4], v[4];
        gate(h4.x, g4.x, a[0], v[0]);
        gate(h4.y, g4.y, a[1], v[1]);
        gate(h4.z, g4.z, a[2], v[2]);
        gate(h4.w, g4.w, a[3], v[3]);

        float A = a[0], V = v[0];
        #pragma unroll
        for (int i = 1; i < 4; i++) { V = fmaf(a[i], V, v[i]); A *= a[i]; }

        #pragma unroll
        for (int off = 1; off < 32; off <<= 1) {
            float Au = __shfl_up_sync(0xffffffffu, A, off);
            float Vu = __shfl_up_sync(0xffffffffu, V, off);
            if (lane >= off) { V = fmaf(A, Vu, V); A *= Au; }
        }
        if (lane == 31) { totA[warp] = A; totV[warp] = V; }
        __syncthreads();

        float Hp = carryH;
        for (int j = 0; j < warp; j++) Hp = fmaf(totA[j], Hp, totV[j]);

        float Ae = __shfl_up_sync(0xffffffffu, A, 1);
        float Ve = __shfl_up_sync(0xffffffffu, V, 1);
        float H = (lane == 0) ? Hp : fmaf(Ae, Hp, Ve);

        float o0, o1, o2, o3;
        H = fmaf(a[0], H, v[0]); o0 = H;
        H = fmaf(a[1], H, v[1]); o1 = H;
        H = fmaf(a[2], H, v[2]); o2 = H;
        H = fmaf(a[3], H, v[3]); o3 = H;

        if (dir == 0) {
            *(float4*)(op + base) = make_float4(o0, o1, o2, o3);
        } else {
            *(float4*)(op + (L_SEQ - 4 - base)) = make_float4(o3, o2, o1, o0);
        }

        float Hc = carryH;
        #pragma unroll
        for (int j = 0; j < 8; j++) Hc = fmaf(totA[j], Hc, totV[j]);
        carryH = Hc;
        __syncthreads();
    }
}

// ---------------------------------------------------------------------------
extern "C" void kernel_launch(void* const* d_in, const int* in_sizes, int n_in,
                              void* d_out, int out_size) {
    const float* x = (const float*)d_in[0];   // (8, 512, 8192)
    const float* W = (const float*)d_in[1];   // (1024, 512, 1)
    float* out = (float*)d_out;               // (8, 512, 8192)

    // Idempotent, capture-safe (not a stream op); called unconditionally.
    cudaFuncSetAttribute(gemm_f16_kernel,
                         cudaFuncAttributeMaxDynamicSharedMemorySize, SMEM_TOTAL);

    normalize_w_kernel<<<O_OUT, 128>>>(W);

    dim3 grid(O_OUT / GBM, L_SEQ / GBN, BATCH);   // M fastest for x L2 reuse
    gemm_f16_kernel<<<grid, 256, SMEM_TOTAL>>>(x);

    scan_kernel<<<BATCH * 512, 256>>>(out);
}

// round 14
// speedup vs baseline: 1.4956x; 1.4956x over previous
#include <cuda_runtime.h>
#include <cuda_fp16.h>
#include <cstdint>

#define L_SEQ 8192
#define D_IN  512
#define O_OUT 1024
#define BATCH 8

// Scratch (device-global: allocation-free per harness rules)
__device__ __half g_fb[(size_t)BATCH * O_OUT * L_SEQ];   // 128 MB (fp16)
__device__ __half g_ah[(size_t)O_OUT * D_IN];            // 1 MB   (Wn in fp16)
__device__ int    g_dummy_sink;

// ---------------------------------------------------------------------------
// Kernel 1: normalize W rows -> fp16
// ---------------------------------------------------------------------------
__global__ void normalize_w_kernel(const float* __restrict__ W) {
    int o = blockIdx.x;          // 1024 rows
    int tid = threadIdx.x;       // 128 threads
    const float* row = W + (size_t)o * D_IN;
    float s = 0.f;
    for (int i = tid; i < D_IN; i += 128) { float w = row[i]; s = fmaf(w, w, s); }
    #pragma unroll
    for (int off = 16; off; off >>= 1) s += __shfl_xor_sync(0xffffffffu, s, off);
    __shared__ float red[4];
    if ((tid & 31) == 0) red[tid >> 5] = s;
    __syncthreads();
    float tot = red[0] + red[1] + red[2] + red[3];
    // Wn = W / (EPS + ||W||/sqrt(fan)) / sqrt(fan) = W / (EPS*sqrt(fan) + ||W||)
    float inv = 1.0f / (1e-4f * sqrtf((float)D_IN) + sqrtf(tot));
    for (int i = tid; i < D_IN; i += 128)
        g_ah[(size_t)o * D_IN + i] = __float2half_rn(row[i] * inv);
}

// Dummy launch to shift ncu's skip-count onto the GEMM (profiling aid only).
__global__ void dummy_kernel() { g_dummy_sink = 1; }

// ---------------------------------------------------------------------------
// Kernel 2: GEMM fb = Wn @ x, fp16 HMMA, K=512, fused f32->fp16 B conversion.
// CTA tile 128x128, 256 threads (8 warps 2x4, warp tile 64x32), 2 CTAs/SM.
// 3-stage ring, write-ahead distance 2: iter it computes from buf[it%3] while
// STS B(it+2) + cp.async A(it+2) write buf[(it+2)%3] (readers retired at the
// previous barrier). wait_group 1 waits the group committed LAST iteration
// (A(it+1)) -> one barrier per iter AND a full iteration of cp.async cover
// (R12 had the single barrier but drained the just-issued group -> regressed).
// ---------------------------------------------------------------------------
#define GBM 128
#define GBN 128
#define GBK 32
#define ITERS (D_IN / GBK)        // 16

#define LDA 40                    // halves per A smem row (32 + pad 8)
#define LDB 136                   // halves per B smem row (128 + pad 8)
#define A_SZ (GBM * LDA * 2)      // 10240
#define B_SZ (GBK * LDB * 2)      // 8704
#define STAGE_SZ (A_SZ + B_SZ)    // 18944
#define SMEM_TOTAL (3 * STAGE_SZ) // 56832

__device__ __forceinline__ uint32_t smem_u32(const void* p) {
    uint32_t a;
    asm("{ .reg .u64 t; cvta.to.shared.u64 t, %1; cvt.u32.u64 %0, t; }" : "=r"(a) : "l"(p));
    return a;
}
__device__ __forceinline__ void cp16(uint32_t dst, const void* src) {
    asm volatile("cp.async.cg.shared.global [%0], [%1], 16;" :: "r"(dst), "l"(src));
}
__device__ __forceinline__ void ldsm_x4(uint32_t* r, uint32_t addr) {
    asm volatile("ldmatrix.sync.aligned.m8n8.x4.shared.b16 {%0,%1,%2,%3}, [%4];"
        : "=r"(r[0]), "=r"(r[1]), "=r"(r[2]), "=r"(r[3]) : "r"(addr));
}
__device__ __forceinline__ void ldsm_x4_t(uint32_t* r, uint32_t addr) {
    asm volatile("ldmatrix.sync.aligned.m8n8.x4.trans.shared.b16 {%0,%1,%2,%3}, [%4];"
        : "=r"(r[0]), "=r"(r[1]), "=r"(r[2]), "=r"(r[3]) : "r"(addr));
}
__device__ __forceinline__ void mma_f16(float* c, const uint32_t* a, uint32_t b0, uint32_t b1) {
    asm volatile("mma.sync.aligned.m16n8k16.row.col.f32.f16.f16.f32 "
        "{%0,%1,%2,%3}, {%4,%5,%6,%7}, {%8,%9}, {%0,%1,%2,%3};"
        : "+f"(c[0]), "+f"(c[1]), "+f"(c[2]), "+f"(c[3])
        : "r"(a[0]), "r"(a[1]), "r"(a[2]), "r"(a[3]), "r"(b0), "r"(b1));
}

// A stage: 128 rows x 32 halves = 512 x 16B chunks, 2 per thread
__device__ __forceinline__ void load_stage_A(uint32_t sb, int m0, int ld, int tid) {
    const uint32_t st = sb + (uint32_t)(ld % 3) * STAGE_SZ;
    #pragma unroll
    for (int j = 0; j < 2; j++) {
        int idx = tid + j * 256;
        int row = idx >> 2, ch = idx & 3;
        cp16(st + row * (LDA * 2) + ch * 16,
             g_ah + (size_t)(m0 + row) * D_IN + ld * GBK + ch * 8);
    }
}

__global__ void __launch_bounds__(256, 2) gemm_f16_kernel(const float* __restrict__ x) {
    extern __shared__ char smem[];
    const uint32_t sb = smem_u32(smem);

    const int tid  = threadIdx.x;
    const int lane = tid & 31;
    const int warp = tid >> 5;
    const int wm = warp >> 2;               // 0..1  (64-row slab)
    const int wn = warp & 3;                // 0..3  (32-col slab)
    const int m0 = blockIdx.x * GBM;        // M fastest -> x stripe L2 reuse
    const int n0 = blockIdx.y * GBN;
    const int b  = blockIdx.z;
    const float* xb = x + (size_t)b * D_IN * L_SEQ;

    // B load mapping: 32 k-rows x 128 f32 = 1024 x 16B chunks, 4 per thread
    int brow[4], bch[4];
    #pragma unroll
    for (int j = 0; j < 4; j++) {
        int idx = tid + j * 256;
        brow[j] = idx >> 5;
        bch[j]  = idx & 31;
    }

    float acc[4][4][4];
    #pragma unroll
    for (int mt = 0; mt < 4; mt++)
        #pragma unroll
        for (int nn = 0; nn < 4; nn++)
            #pragma unroll
            for (int i = 0; i < 4; i++) acc[mt][nn][i] = 0.f;

    float4 bReg[4];
    auto ldg_B = [&](int it) {
        const int k0 = it * GBK;
        #pragma unroll
        for (int j = 0; j < 4; j++)
            bReg[j] = *(const float4*)(xb + (size_t)(k0 + brow[j]) * L_SEQ + n0 + bch[j] * 4);
    };
    auto sts_B = [&](int slot) {
        char* bp = smem + slot * STAGE_SZ + A_SZ;
        #pragma unroll
        for (int j = 0; j < 4; j++) {
            float4 v = bReg[j];
            __half2 h0 = __floats2half2_rn(v.x, v.y);
            __half2 h1 = __floats2half2_rn(v.z, v.w);
            *(uint2*)(bp + brow[j] * (LDB * 2) + bch[j] * 8)
                = make_uint2(*(uint32_t*)&h0, *(uint32_t*)&h1);
        }
    };

    // ---- prologue: stages 0 and 1 resident, B(2) in regs ----
    ldg_B(0); sts_B(0);
    load_stage_A(sb, m0, 0, tid);
    asm volatile("cp.async.commit_group;");
    ldg_B(1); sts_B(1);
    load_stage_A(sb, m0, 1, tid);
    asm volatile("cp.async.commit_group;");
    ldg_B(2);
    asm volatile("cp.async.wait_group 1;");   // A(0) resident
    __syncthreads();

    #pragma unroll 1
    for (int it = 0; it < ITERS; ++it) {
        const uint32_t st = sb + (uint32_t)(it % 3) * STAGE_SZ;

        // ---- write-ahead distance 2 (readers retired at previous barrier) ----
        if (it + 2 < ITERS) {
            sts_B((it + 2) % 3);                 // bReg holds B(it+2)
            load_stage_A(sb, m0, it + 2, tid);   // A(it+2) cp.async
        }
        asm volatile("cp.async.commit_group;");  // fixed group count
        if (it + 3 < ITERS) ldg_B(it + 3);       // B(it+3) -> regs, 1 iter of cover

        // ---- compute(it) from current buffer ----
        #pragma unroll
        for (int kk = 0; kk < 2; kk++) {
            uint32_t af[4][4];
            #pragma unroll
            for (int mt = 0; mt < 4; mt++) {
                int row = wm * 64 + mt * 16 + (lane & 15);
                int col = kk * 16 + (lane >> 4) * 8;
                ldsm_x4(af[mt], st + (row * LDA + col) * 2);
            }
            uint32_t bf[2][4];
            #pragma unroll
            for (int ng = 0; ng < 2; ng++) {
                int krow = kk * 16 + (lane & 15);
                int col  = wn * 32 + ng * 16 + (lane >> 4) * 8;
                ldsm_x4_t(bf[ng], st + A_SZ + (krow * LDB + col) * 2);
            }
            #pragma unroll
            for (int mt = 0; mt < 4; mt++)
                #pragma unroll
                for (int ng = 0; ng < 2; ng++) {
                    mma_f16(acc[mt][2 * ng + 0], af[mt], bf[ng][0], bf[ng][1]);
                    mma_f16(acc[mt][2 * ng + 1], af[mt], bf[ng][2], bf[ng][3]);
                }
        }

        // ---- single barrier: waits group committed LAST iter (A(it+1)) ----
        asm volatile("cp.async.wait_group 1;");
        __syncthreads();
    }

    // epilogue -> g_fb (fp16)
    __half* fbb = g_fb + (size_t)b * O_OUT * L_SEQ;
    #pragma unroll
    for (int mt = 0; mt < 4; mt++) {
        int row = m0 + wm * 64 + mt * 16 + (lane >> 2);
        #pragma unroll
        for (int nn = 0; nn < 4; nn++) {
            int col = n0 + wn * 32 + nn * 8 + (lane & 3) * 2;
            __half2 v01 = __floats2half2_rn(acc[mt][nn][0], acc[mt][nn][1]);
            __half2 v23 = __floats2half2_rn(acc[mt][nn][2], acc[mt][nn][3]);
            *(__half2*)&fbb[(size_t)row * L_SEQ + col]       = v01;
            *(__half2*)&fbb[(size_t)(row + 8) * L_SEQ + col] = v23;
        }
    }
}

// ---------------------------------------------------------------------------
// Kernel 3: parallel linear-recurrence scan (fwd + bwd), H_t = a*H_{t-1} + v
// ---------------------------------------------------------------------------
__device__ __forceinline__ void gate(float h, float g, float& a, float& v) {
    float en = __expf(-fabsf(g));               // e^{-|g|} (fast path, ~2 ulp)
    float q  = rsqrtf(fmaf(en, en, 1.0f));      // 1/sqrt(1+en^2)
    float eq = en * q;
    bool pos = (g >= 0.f);
    a = pos ? eq : q;           // sigma(-g)*sqrt(1+sech g)
    v = (pos ? q : eq) * h;     // sigma(g)*sqrt(1+sech g)*h
}

__device__ __forceinline__ float4 load_h4(const __half* p, int rev) {
    uint2 u = *(const uint2*)p;
    __half2* hh = (__half2*)&u;
    float2 p0 = __half22float2(hh[0]);
    float2 p1 = __half22float2(hh[1]);
    if (!rev) return make_float4(p0.x, p0.y, p1.x, p1.y);
    return make_float4(p1.y, p1.x, p0.y, p0.x);
}

__global__ void __launch_bounds__(256) scan_kernel(float* __restrict__ out) {
    const int sid = blockIdx.x;            // 0..4095
    const int b   = sid >> 9;
    const int rem = sid & 511;
    const int dir = rem >> 8;              // 0 fwd, 1 bwd
    const int ch  = rem & 255;

    const __half* hp = g_fb + ((size_t)b * O_OUT + (size_t)dir * 512 + ch) * L_SEQ;
    const __half* gp = hp + (size_t)256 * L_SEQ;
    float* op = out + ((size_t)b * 512 + (size_t)dir * 256 + ch) * L_SEQ;

    const int tid = threadIdx.x;
    const int lane = tid & 31;
    const int warp = tid >> 5;

    __shared__ float totA[8], totV[8];
    float carryH = 0.f;

    #pragma unroll 1
    for (int s = 0; s < L_SEQ / 1024; ++s) {
        const int base = s * 1024 + tid * 4;
        float4 h4, g4;
        if (dir == 0) {
            h4 = load_h4(hp + base, 0);
            g4 = load_h4(gp + base, 0);
        } else {
            int gi = L_SEQ - 4 - base;
            h4 = load_h4(hp + gi, 1);
            g4 = load_h4(gp + gi, 1);
        }

        float a[4], v[4];
        gate(h4.x, g4.x, a[0], v[0]);
        gate(h4.y, g4.y, a[1], v[1]);
        gate(h4.z, g4.z, a[2], v[2]);
        gate(h4.w, g4.w, a[3], v[3]);

        float A = a[0], V = v[0];
        #pragma unroll
        for (int i = 1; i < 4; i++) { V = fmaf(a[i], V, v[i]); A *= a[i]; }

        #pragma unroll
        for (int off = 1; off < 32; off <<= 1) {
            float Au = __shfl_up_sync(0xffffffffu, A, off);
            float Vu = __shfl_up_sync(0xffffffffu, V, off);
            if (lane >= off) { V = fmaf(A, Vu, V); A *= Au; }
        }
        if (lane == 31) { totA[warp] = A; totV[warp] = V; }
        __syncthreads();

        float Hp = carryH;
        for (int j = 0; j < warp; j++) Hp = fmaf(totA[j], Hp, totV[j]);

        float Ae = __shfl_up_sync(0xffffffffu, A, 1);
        float Ve = __shfl_up_sync(0xffffffffu, V, 1);
        float H = (lane == 0) ? Hp : fmaf(Ae, Hp, Ve);

        float o0, o1, o2, o3;
        H = fmaf(a[0], H, v[0]); o0 = H;
        H = fmaf(a[1], H, v[1]); o1 = H;
        H = fmaf(a[2], H, v[2]); o2 = H;
        H = fmaf(a[3], H, v[3]); o3 = H;

        if (dir == 0) {
            *(float4*)(op + base) = make_float4(o0, o1, o2, o3);
        } else {
            *(float4*)(op + (L_SEQ - 4 - base)) = make_float4(o3, o2, o1, o0);
        }

        float Hc = carryH;
        #pragma unroll
        for (int j = 0; j < 8; j++) Hc = fmaf(totA[j], Hc, totV[j]);
        carryH = Hc;
        __syncthreads();
    }
}

// ---------------------------------------------------------------------------
extern "C" void kernel_launch(void* const* d_in, const int* in_sizes, int n_in,
                              void* d_out, int out_size) {
    const float* x = (const float*)d_in[0];   // (8, 512, 8192)
    const float* W = (const float*)d_in[1];   // (1024, 512, 1)
    float* out = (float*)d_out;               // (8, 512, 8192)

    // Idempotent, capture-safe (not a stream op); called unconditionally.
    cudaFuncSetAttribute(gemm_f16_kernel,
                         cudaFuncAttributeMaxDynamicSharedMemorySize, SMEM_TOTAL);

    normalize_w_kernel<<<O_OUT, 128>>>(W);

    dim3 grid(O_OUT / GBM, L_SEQ / GBN, BATCH);   // M fastest for x L2 reuse
    gemm_f16_kernel<<<grid, 256, SMEM_TOTAL>>>(x);

    scan_kernel<<<BATCH * 512, 256>>>(out);

    // 4th launch per call: shifts ncu's "-s 5" capture onto call-1's GEMM.
    dummy_kernel<<<1, 1>>>();
}

// round 16
// speedup vs baseline: 1.5718x; 1.0509x over previous
#include <cuda_runtime.h>
#include <cuda_fp16.h>
#include <cstdint>

#define L_SEQ 8192
#define D_IN  512
#define O_OUT 1024
#define BATCH 8

// Scratch (device-global: allocation-free per harness rules)
__device__ __half g_fb[(size_t)BATCH * O_OUT * L_SEQ];   // 128 MB (fp16)
__device__ __half g_ah[(size_t)O_OUT * D_IN];            // 1 MB   (Wn in fp16)

// ---------------------------------------------------------------------------
// Kernel 1: normalize W rows -> fp16
// ---------------------------------------------------------------------------
__global__ void normalize_w_kernel(const float* __restrict__ W) {
    int o = blockIdx.x;          // 1024 rows
    int tid = threadIdx.x;       // 128 threads
    const float* row = W + (size_t)o * D_IN;
    float s = 0.f;
    for (int i = tid; i < D_IN; i += 128) { float w = row[i]; s = fmaf(w, w, s); }
    #pragma unroll
    for (int off = 16; off; off >>= 1) s += __shfl_xor_sync(0xffffffffu, s, off);
    __shared__ float red[4];
    if ((tid & 31) == 0) red[tid >> 5] = s;
    __syncthreads();
    float tot = red[0] + red[1] + red[2] + red[3];
    // Wn = W / (EPS + ||W||/sqrt(fan)) / sqrt(fan) = W / (EPS*sqrt(fan) + ||W||)
    float inv = 1.0f / (1e-4f * sqrtf((float)D_IN) + sqrtf(tot));
    for (int i = tid; i < D_IN; i += 128)
        g_ah[(size_t)o * D_IN + i] = __float2half_rn(row[i] * inv);
}

// ---------------------------------------------------------------------------
// Kernel 2: GEMM fb = Wn @ x, fp16 HMMA, K=512, fused f32->fp16 B conversion.
// CTA tile 128x128, 128 threads (4 warps 2x2, warp tile 64x64), 2 CTAs/SM.
// 64x64 warp tile doubles MMA:ldsm ratio (4:1 vs 2.67:1) -- R11/R14 showed the
// GEMM pinned at ~247us regardless of pipeline structure; wavefront accounting
// says the L1/shared port (ldsm + B LDG/STS) was the binding pipe, not HMMA.
// 3-stage ring, write-ahead distance 2, single barrier per iter (R14 struct).
// ---------------------------------------------------------------------------
#define GBM 128
#define GBN 128
#define GBK 32
#define ITERS (D_IN / GBK)        // 16
#define NT 128                    // threads per CTA

#define LDA 40                    // halves per A smem row (32 + pad 8)
#define LDB 136                   // halves per B smem row (128 + pad 8)
#define A_SZ (GBM * LDA * 2)      // 10240
#define B_SZ (GBK * LDB * 2)      // 8704
#define STAGE_SZ (A_SZ + B_SZ)    // 18944
#define SMEM_TOTAL (3 * STAGE_SZ) // 56832

__device__ __forceinline__ uint32_t smem_u32(const void* p) {
    uint32_t a;
    asm("{ .reg .u64 t; cvta.to.shared.u64 t, %1; cvt.u32.u64 %0, t; }" : "=r"(a) : "l"(p));
    return a;
}
__device__ __forceinline__ void cp16(uint32_t dst, const void* src) {
    asm volatile("cp.async.cg.shared.global [%0], [%1], 16;" :: "r"(dst), "l"(src));
}
__device__ __forceinline__ void ldsm_x4(uint32_t* r, uint32_t addr) {
    asm volatile("ldmatrix.sync.aligned.m8n8.x4.shared.b16 {%0,%1,%2,%3}, [%4];"
        : "=r"(r[0]), "=r"(r[1]), "=r"(r[2]), "=r"(r[3]) : "r"(addr));
}
__device__ __forceinline__ void ldsm_x4_t(uint32_t* r, uint32_t addr) {
    asm volatile("ldmatrix.sync.aligned.m8n8.x4.trans.shared.b16 {%0,%1,%2,%3}, [%4];"
        : "=r"(r[0]), "=r"(r[1]), "=r"(r[2]), "=r"(r[3]) : "r"(addr));
}
__device__ __forceinline__ void mma_f16(float* c, const uint32_t* a, uint32_t b0, uint32_t b1) {
    asm volatile("mma.sync.aligned.m16n8k16.row.col.f32.f16.f16.f32 "
        "{%0,%1,%2,%3}, {%4,%5,%6,%7}, {%8,%9}, {%0,%1,%2,%3};"
        : "+f"(c[0]), "+f"(c[1]), "+f"(c[2]), "+f"(c[3])
        : "r"(a[0]), "r"(a[1]), "r"(a[2]), "r"(a[3]), "r"(b0), "r"(b1));
}

// A stage: 128 rows x 32 halves = 512 x 16B chunks, 4 per thread
__device__ __forceinline__ void load_stage_A(uint32_t sb, int m0, int ld, int tid) {
    const uint32_t st = sb + (uint32_t)(ld % 3) * STAGE_SZ;
    #pragma unroll
    for (int j = 0; j < 4; j++) {
        int idx = tid + j * NT;
        int row = idx >> 2, ch = idx & 3;
        cp16(st + row * (LDA * 2) + ch * 16,
             g_ah + (size_t)(m0 + row) * D_IN + ld * GBK + ch * 8);
    }
}

__global__ void __launch_bounds__(NT, 2) gemm_f16_kernel(const float* __restrict__ x) {
    extern __shared__ char smem[];
    const uint32_t sb = smem_u32(smem);

    const int tid  = threadIdx.x;
    const int lane = tid & 31;
    const int warp = tid >> 5;
    const int wm = warp >> 1;               // 0..1  (64-row slab)
    const int wn = warp & 1;                // 0..1  (64-col slab)
    const int m0 = blockIdx.x * GBM;        // M fastest -> x stripe L2 reuse
    const int n0 = blockIdx.y * GBN;
    const int b  = blockIdx.z;
    const float* xb = x + (size_t)b * D_IN * L_SEQ;

    // B load mapping: 32 k-rows x 128 f32 = 1024 x 16B chunks, 8 per thread
    int brow[8], bch[8];
    #pragma unroll
    for (int j = 0; j < 8; j++) {
        int idx = tid + j * NT;
        brow[j] = idx >> 5;
        bch[j]  = idx & 31;
    }

    float acc[4][8][4];
    #pragma unroll
    for (int mt = 0; mt < 4; mt++)
        #pragma unroll
        for (int nn = 0; nn < 8; nn++)
            #pragma unroll
            for (int i = 0; i < 4; i++) acc[mt][nn][i] = 0.f;

    float4 bReg[8];
    auto ldg_B = [&](int it) {
        const int k0 = it * GBK;
        #pragma unroll
        for (int j = 0; j < 8; j++)
            bReg[j] = *(const float4*)(xb + (size_t)(k0 + brow[j]) * L_SEQ + n0 + bch[j] * 4);
    };
    auto sts_B = [&](int slot) {
        char* bp = smem + slot * STAGE_SZ + A_SZ;
        #pragma unroll
        for (int j = 0; j < 8; j++) {
            float4 v = bReg[j];
            __half2 h0 = __floats2half2_rn(v.x, v.y);
            __half2 h1 = __floats2half2_rn(v.z, v.w);
            *(uint2*)(bp + brow[j] * (LDB * 2) + bch[j] * 8)
                = make_uint2(*(uint32_t*)&h0, *(uint32_t*)&h1);
        }
    };

    // ---- prologue: stages 0 and 1 resident, B(2) in regs ----
    ldg_B(0); sts_B(0);
    load_stage_A(sb, m0, 0, tid);
    asm volatile("cp.async.commit_group;");
    ldg_B(1); sts_B(1);
    load_stage_A(sb, m0, 1, tid);
    asm volatile("cp.async.commit_group;");
    ldg_B(2);
    asm volatile("cp.async.wait_group 1;");   // A(0) resident
    __syncthreads();

    #pragma unroll 1
    for (int it = 0; it < ITERS; ++it) {
        const uint32_t st = sb + (uint32_t)(it % 3) * STAGE_SZ;

        // ---- write-ahead distance 2 (readers retired at previous barrier) ----
        if (it + 2 < ITERS) {
            sts_B((it + 2) % 3);                 // bReg holds B(it+2)
            load_stage_A(sb, m0, it + 2, tid);   // A(it+2) cp.async
        }
        asm volatile("cp.async.commit_group;");  // fixed group count
        if (it + 3 < ITERS) ldg_B(it + 3);       // B(it+3) -> regs, 1 iter of cover

        // ---- compute(it): 64x64 warp tile, 16 ldsm / 64 MMA per iter ----
        #pragma unroll
        for (int kk = 0; kk < 2; kk++) {
            uint32_t af[4][4];
            #pragma unroll
            for (int mt = 0; mt < 4; mt++) {
                int row = wm * 64 + mt * 16 + (lane & 15);
                int col = kk * 16 + (lane >> 4) * 8;
                ldsm_x4(af[mt], st + (row * LDA + col) * 2);
            }
            uint32_t bf[4][4];
            #pragma unroll
            for (int ng = 0; ng < 4; ng++) {
                int krow = kk * 16 + (lane & 15);
                int col  = wn * 64 + ng * 16 + (lane >> 4) * 8;
                ldsm_x4_t(bf[ng], st + A_SZ + (krow * LDB + col) * 2);
            }
            #pragma unroll
            for (int mt = 0; mt < 4; mt++)
                #pragma unroll
                for (int ng = 0; ng < 4; ng++) {
                    mma_f16(acc[mt][2 * ng + 0], af[mt], bf[ng][0], bf[ng][1]);
                    mma_f16(acc[mt][2 * ng + 1], af[mt], bf[ng][2], bf[ng][3]);
                }
        }

        // ---- single barrier: waits group committed LAST iter (A(it+1)) ----
        asm volatile("cp.async.wait_group 1;");
        __syncthreads();
    }

    // epilogue -> g_fb (fp16)
    __half* fbb = g_fb + (size_t)b * O_OUT * L_SEQ;
    #pragma unroll
    for (int mt = 0; mt < 4; mt++) {
        int row = m0 + wm * 64 + mt * 16 + (lane >> 2);
        #pragma unroll
        for (int nn = 0; nn < 8; nn++) {
            int col = n0 + wn * 64 + nn * 8 + (lane & 3) * 2;
            __half2 v01 = __floats2half2_rn(acc[mt][nn][0], acc[mt][nn][1]);
            __half2 v23 = __floats2half2_rn(acc[mt][nn][2], acc[mt][nn][3]);
            *(__half2*)&fbb[(size_t)row * L_SEQ + col]       = v01;
            *(__half2*)&fbb[(size_t)(row + 8) * L_SEQ + col] = v23;
        }
    }
}

// ---------------------------------------------------------------------------
// Kernel 3: parallel linear-recurrence scan (fwd + bwd), H_t = a*H_{t-1} + v
// ---------------------------------------------------------------------------
__device__ __forceinline__ void gate(float h, float g, float& a, float& v) {
    float en = __expf(-fabsf(g));               // e^{-|g|} (fast path, ~2 ulp)
    float q  = rsqrtf(fmaf(en, en, 1.0f));      // 1/sqrt(1+en^2)
    float eq = en * q;
    bool pos = (g >= 0.f);
    a = pos ? eq : q;           // sigma(-g)*sqrt(1+sech g)
    v = (pos ? q : eq) * h;     // sigma(g)*sqrt(1+sech g)*h
}

__device__ __forceinline__ float4 load_h4(const __half* p, int rev) {
    uint2 u = *(const uint2*)p;
    __half2* hh = (__half2*)&u;
    float2 p0 = __half22float2(hh[0]);
    float2 p1 = __half22float2(hh[1]);
    if (!rev) return make_float4(p0.x, p0.y, p1.x, p1.y);
    return make_float4(p1.y, p1.x, p0.y, p0.x);
}

__global__ void __launch_bounds__(256) scan_kernel(float* __restrict__ out) {
    const int sid = blockIdx.x;            // 0..4095
    const int b   = sid >> 9;
    const int rem = sid & 511;
    const int dir = rem >> 8;              // 0 fwd, 1 bwd
    const int ch  = rem & 255;

    const __half* hp = g_fb + ((size_t)b * O_OUT + (size_t)dir * 512 + ch) * L_SEQ;
    const __half* gp = hp + (size_t)256 * L_SEQ;
    float* op = out + ((size_t)b * 512 + (size_t)dir * 256 + ch) * L_SEQ;

    const int tid = threadIdx.x;
    const int lane = tid & 31;
    const int warp = tid >> 5;

    __shared__ float totA[8], totV[8];
    float carryH = 0.f;

    #pragma unroll 1
    for (int s = 0; s < L_SEQ / 1024; ++s) {
        const int base = s * 1024 + tid * 4;
        float4 h4, g4;
        if (dir == 0) {
            h4 = load_h4(hp + base, 0);
            g4 = load_h4(gp + base, 0);
        } else {
            int gi = L_SEQ - 4 - base;
            h4 = load_h4(hp + gi, 1);
            g4 = load_h4(gp + gi, 1);
        }

        float a[4], v[4];
        gate(h4.x, g4.x, a[0], v[0]);
        gate(h4.y, g4.y, a[1], v[1]);
        gate(h4.z, g4.z, a[2], v[2]);
        gate(h4.w, g4.w, a[3], v[3]);

        float A = a[0], V = v[0];
        #pragma unroll
        for (int i = 1; i < 4; i++) { V = fmaf(a[i], V, v[i]); A *= a[i]; }

        #pragma unroll
        for (int off = 1; off < 32; off <<= 1) {
            float Au = __shfl_up_sync(0xffffffffu, A, off);
            float Vu = __shfl_up_sync(0xffffffffu, V, off);
            if (lane >= off) { V = fmaf(A, Vu, V); A *= Au; }
        }
        if (lane == 31) { totA[warp] = A; totV[warp] = V; }
        __syncthreads();

        float Hp = carryH;
        for (int j = 0; j < warp; j++) Hp = fmaf(totA[j], Hp, totV[j]);

        float Ae = __shfl_up_sync(0xffffffffu, A, 1);
        float Ve = __shfl_up_sync(0xffffffffu, V, 1);
        float H = (lane == 0) ? Hp : fmaf(Ae, Hp, Ve);

        float o0, o1, o2, o3;
        H = fmaf(a[0], H, v[0]); o0 = H;
        H = fmaf(a[1], H, v[1]); o1 = H;
        H = fmaf(a[2], H, v[2]); o2 = H;
        H = fmaf(a[3], H, v[3]); o3 = H;

        if (dir == 0) {
            *(float4*)(op + base) = make_float4(o0, o1, o2, o3);
        } else {
            *(float4*)(op + (L_SEQ - 4 - base)) = make_float4(o3, o2, o1, o0);
        }

        float Hc = carryH;
        #pragma unroll
        for (int j = 0; j < 8; j++) Hc = fmaf(totA[j], Hc, totV[j]);
        carryH = Hc;
        __syncthreads();
    }
}

// ---------------------------------------------------------------------------
extern "C" void kernel_launch(void* const* d_in, const int* in_sizes, int n_in,
                              void* d_out, int out_size) {
    const float* x = (const float*)d_in[0];   // (8, 512, 8192)
    const float* W = (const float*)d_in[1];   // (1024, 512, 1)
    float* out = (float*)d_out;               // (8, 512, 8192)

    // Idempotent, capture-safe (not a stream op); called unconditionally.
    cudaFuncSetAttribute(gemm_f16_kernel,
                         cudaFuncAttributeMaxDynamicSharedMemorySize, SMEM_TOTAL);

    normalize_w_kernel<<<O_OUT, 128>>>(W);

    dim3 grid(O_OUT / GBM, L_SEQ / GBN, BATCH);   // M fastest for x L2 reuse
    gemm_f16_kernel<<<grid, NT, SMEM_TOTAL>>>(x);

    scan_kernel<<<BATCH * 512, 256>>>(out);
}

// round 17
// speedup vs baseline: 1.6196x; 1.0304x over previous
#include <cuda_runtime.h>
#include <cuda_fp16.h>
#include <cstdint>

#define L_SEQ 8192
#define D_IN  512
#define O_OUT 1024
#define BATCH 8

// Scratch (device-global: allocation-free per harness rules)
__device__ __half g_fb[(size_t)BATCH * O_OUT * L_SEQ];   // 128 MB (fp16)
__device__ __half g_ah[(size_t)O_OUT * D_IN];            // 1 MB   (Wn in fp16)

// ---------------------------------------------------------------------------
// Kernel 1: normalize W rows -> fp16
// ---------------------------------------------------------------------------
__global__ void normalize_w_kernel(const float* __restrict__ W) {
    int o = blockIdx.x;          // 1024 rows
    int tid = threadIdx.x;       // 128 threads
    const float* row = W + (size_t)o * D_IN;
    float s = 0.f;
    for (int i = tid; i < D_IN; i += 128) { float w = row[i]; s = fmaf(w, w, s); }
    #pragma unroll
    for (int off = 16; off; off >>= 1) s += __shfl_xor_sync(0xffffffffu, s, off);
    __shared__ float red[4];
    if ((tid & 31) == 0) red[tid >> 5] = s;
    __syncthreads();
    float tot = red[0] + red[1] + red[2] + red[3];
    // Wn = W / (EPS + ||W||/sqrt(fan)) / sqrt(fan) = W / (EPS*sqrt(fan) + ||W||)
    float inv = 1.0f / (1e-4f * sqrtf((float)D_IN) + sqrtf(tot));
    for (int i = tid; i < D_IN; i += 128)
        g_ah[(size_t)o * D_IN + i] = __float2half_rn(row[i] * inv);
}

// ---------------------------------------------------------------------------
// Kernel 2: GEMM fb = Wn @ x, fp16 HMMA, K=512, fused f32->fp16 B conversion.
// CTA tile 128x128, 128 threads (4 warps 2x2, warp tile 64x64), 2 CTAs/SM.
// 3-stage ring, write-ahead distance 2, single barrier per iter (R16 struct,
// measured locally optimal). NEW: epilogue stages the output tile in smem
// (reusing pipeline buffers) and writes fully-coalesced uint4 rows -- the old
// direct __half2 stores splintered into 16B sectors (~8M wavefronts).
// ---------------------------------------------------------------------------
#define GBM 128
#define GBN 128
#define GBK 32
#define ITERS (D_IN / GBK)        // 16
#define NT 128                    // threads per CTA

#define LDA 40                    // halves per A smem row (32 + pad 8)
#define LDB 136                   // halves per B smem row (128 + pad 8)
#define A_SZ (GBM * LDA * 2)      // 10240
#define B_SZ (GBK * LDB * 2)      // 8704
#define STAGE_SZ (A_SZ + B_SZ)    // 18944
#define SMEM_TOTAL (3 * STAGE_SZ) // 56832
#define ELD 136                   // epilogue tile stride (halves)

__device__ __forceinline__ uint32_t smem_u32(const void* p) {
    uint32_t a;
    asm("{ .reg .u64 t; cvta.to.shared.u64 t, %1; cvt.u32.u64 %0, t; }" : "=r"(a) : "l"(p));
    return a;
}
__device__ __forceinline__ void cp16(uint32_t dst, const void* src) {
    asm volatile("cp.async.cg.shared.global [%0], [%1], 16;" :: "r"(dst), "l"(src));
}
__device__ __forceinline__ void ldsm_x4(uint32_t* r, uint32_t addr) {
    asm volatile("ldmatrix.sync.aligned.m8n8.x4.shared.b16 {%0,%1,%2,%3}, [%4];"
        : "=r"(r[0]), "=r"(r[1]), "=r"(r[2]), "=r"(r[3]) : "r"(addr));
}
__device__ __forceinline__ void ldsm_x4_t(uint32_t* r, uint32_t addr) {
    asm volatile("ldmatrix.sync.aligned.m8n8.x4.trans.shared.b16 {%0,%1,%2,%3}, [%4];"
        : "=r"(r[0]), "=r"(r[1]), "=r"(r[2]), "=r"(r[3]) : "r"(addr));
}
__device__ __forceinline__ void mma_f16(float* c, const uint32_t* a, uint32_t b0, uint32_t b1) {
    asm volatile("mma.sync.aligned.m16n8k16.row.col.f32.f16.f16.f32 "
        "{%0,%1,%2,%3}, {%4,%5,%6,%7}, {%8,%9}, {%0,%1,%2,%3};"
        : "+f"(c[0]), "+f"(c[1]), "+f"(c[2]), "+f"(c[3])
        : "r"(a[0]), "r"(a[1]), "r"(a[2]), "r"(a[3]), "r"(b0), "r"(b1));
}

// A stage: 128 rows x 32 halves = 512 x 16B chunks, 4 per thread
__device__ __forceinline__ void load_stage_A(uint32_t sb, int m0, int ld, int tid) {
    const uint32_t st = sb + (uint32_t)(ld % 3) * STAGE_SZ;
    #pragma unroll
    for (int j = 0; j < 4; j++) {
        int idx = tid + j * NT;
        int row = idx >> 2, ch = idx & 3;
        cp16(st + row * (LDA * 2) + ch * 16,
             g_ah + (size_t)(m0 + row) * D_IN + ld * GBK + ch * 8);
    }
}

__global__ void __launch_bounds__(NT, 2) gemm_f16_kernel(const float* __restrict__ x) {
    extern __shared__ char smem[];
    const uint32_t sb = smem_u32(smem);

    const int tid  = threadIdx.x;
    const int lane = tid & 31;
    const int warp = tid >> 5;
    const int wm = warp >> 1;               // 0..1  (64-row slab)
    const int wn = warp & 1;                // 0..1  (64-col slab)
    const int m0 = blockIdx.x * GBM;        // M fastest -> x stripe L2 reuse
    const int n0 = blockIdx.y * GBN;
    const int b  = blockIdx.z;
    const float* xb = x + (size_t)b * D_IN * L_SEQ;

    // B load mapping: 32 k-rows x 128 f32 = 1024 x 16B chunks, 8 per thread
    int brow[8], bch[8];
    #pragma unroll
    for (int j = 0; j < 8; j++) {
        int idx = tid + j * NT;
        brow[j] = idx >> 5;
        bch[j]  = idx & 31;
    }

    float acc[4][8][4];
    #pragma unroll
    for (int mt = 0; mt < 4; mt++)
        #pragma unroll
        for (int nn = 0; nn < 8; nn++)
            #pragma unroll
            for (int i = 0; i < 4; i++) acc[mt][nn][i] = 0.f;

    float4 bReg[8];
    auto ldg_B = [&](int it) {
        const int k0 = it * GBK;
        #pragma unroll
        for (int j = 0; j < 8; j++)
            bReg[j] = *(const float4*)(xb + (size_t)(k0 + brow[j]) * L_SEQ + n0 + bch[j] * 4);
    };
    auto sts_B = [&](int slot) {
        char* bp = smem + slot * STAGE_SZ + A_SZ;
        #pragma unroll
        for (int j = 0; j < 8; j++) {
            float4 v = bReg[j];
            __half2 h0 = __floats2half2_rn(v.x, v.y);
            __half2 h1 = __floats2half2_rn(v.z, v.w);
            *(uint2*)(bp + brow[j] * (LDB * 2) + bch[j] * 8)
                = make_uint2(*(uint32_t*)&h0, *(uint32_t*)&h1);
        }
    };

    // ---- prologue: stages 0 and 1 resident, B(2) in regs ----
    ldg_B(0); sts_B(0);
    load_stage_A(sb, m0, 0, tid);
    asm volatile("cp.async.commit_group;");
    ldg_B(1); sts_B(1);
    load_stage_A(sb, m0, 1, tid);
    asm volatile("cp.async.commit_group;");
    ldg_B(2);
    asm volatile("cp.async.wait_group 1;");   // A(0) resident
    __syncthreads();

    #pragma unroll 1
    for (int it = 0; it < ITERS; ++it) {
        const uint32_t st = sb + (uint32_t)(it % 3) * STAGE_SZ;

        // ---- write-ahead distance 2 (readers retired at previous barrier) ----
        if (it + 2 < ITERS) {
            sts_B((it + 2) % 3);                 // bReg holds B(it+2)
            load_stage_A(sb, m0, it + 2, tid);   // A(it+2) cp.async
        }
        asm volatile("cp.async.commit_group;");  // fixed group count
        if (it + 3 < ITERS) ldg_B(it + 3);       // B(it+3) -> regs, 1 iter of cover

        // ---- compute(it): 64x64 warp tile, 16 ldsm / 64 MMA per iter ----
        #pragma unroll
        for (int kk = 0; kk < 2; kk++) {
            uint32_t af[4][4];
            #pragma unroll
            for (int mt = 0; mt < 4; mt++) {
                int row = wm * 64 + mt * 16 + (lane & 15);
                int col = kk * 16 + (lane >> 4) * 8;
                ldsm_x4(af[mt], st + (row * LDA + col) * 2);
            }
            uint32_t bf[4][4];
            #pragma unroll
            for (int ng = 0; ng < 4; ng++) {
                int krow = kk * 16 + (lane & 15);
                int col  = wn * 64 + ng * 16 + (lane >> 4) * 8;
                ldsm_x4_t(bf[ng], st + A_SZ + (krow * LDB + col) * 2);
            }
            #pragma unroll
            for (int mt = 0; mt < 4; mt++)
                #pragma unroll
                for (int ng = 0; ng < 4; ng++) {
                    mma_f16(acc[mt][2 * ng + 0], af[mt], bf[ng][0], bf[ng][1]);
                    mma_f16(acc[mt][2 * ng + 1], af[mt], bf[ng][2], bf[ng][3]);
                }
        }

        // ---- single barrier: waits group committed LAST iter (A(it+1)) ----
        asm volatile("cp.async.wait_group 1;");
        __syncthreads();
    }

    // ---- epilogue: acc -> smem tile (pipeline buffers are dead) -> coalesced STG
    __half* etile = (__half*)smem;
    #pragma unroll
    for (int mt = 0; mt < 4; mt++) {
        int row = wm * 64 + mt * 16 + (lane >> 2);
        #pragma unroll
        for (int nn = 0; nn < 8; nn++) {
            int col = wn * 64 + nn * 8 + (lane & 3) * 2;
            __half2 v01 = __floats2half2_rn(acc[mt][nn][0], acc[mt][nn][1]);
            __half2 v23 = __floats2half2_rn(acc[mt][nn][2], acc[mt][nn][3]);
            *(__half2*)&etile[row * ELD + col]       = v01;
            *(__half2*)&etile[(row + 8) * ELD + col] = v23;
        }
    }
    __syncthreads();
    __half* fbb = g_fb + ((size_t)b * O_OUT + m0) * L_SEQ + n0;
    #pragma unroll
    for (int j = 0; j < 16; j++) {
        int idx = tid + j * NT;          // 0..2047
        int row = idx >> 4, c16 = idx & 15;   // 128 cols = 16 x uint4
        uint4 v = *(uint4*)&etile[row * ELD + c16 * 8];
        *(uint4*)&fbb[(size_t)row * L_SEQ + c16 * 8] = v;
    }
}

// ---------------------------------------------------------------------------
// Kernel 3: parallel linear-recurrence scan (fwd + bwd), H_t = a*H_{t-1} + v
// 8 elems/thread (2048-wide segments): halves shuffle/barrier overhead per
// element vs R16's 4 (scan was issue-bound at 77%).
// ---------------------------------------------------------------------------
__device__ __forceinline__ void gate(float h, float g, float& a, float& v) {
    float en = __expf(-fabsf(g));               // e^{-|g|} (fast path, ~2 ulp)
    float q  = rsqrtf(fmaf(en, en, 1.0f));      // 1/sqrt(1+en^2)
    float eq = en * q;
    bool pos = (g >= 0.f);
    a = pos ? eq : q;           // sigma(-g)*sqrt(1+sech g)
    v = (pos ? q : eq) * h;     // sigma(g)*sqrt(1+sech g)*h
}

__device__ __forceinline__ void load_h8(const __half* p, int rev, float* e) {
    uint4 u = *(const uint4*)p;
    __half2* hh = (__half2*)&u;
    float2 p0 = __half22float2(hh[0]);
    float2 p1 = __half22float2(hh[1]);
    float2 p2 = __half22float2(hh[2]);
    float2 p3 = __half22float2(hh[3]);
    if (!rev) {
        e[0] = p0.x; e[1] = p0.y; e[2] = p1.x; e[3] = p1.y;
        e[4] = p2.x; e[5] = p2.y; e[6] = p3.x; e[7] = p3.y;
    } else {
        e[0] = p3.y; e[1] = p3.x; e[2] = p2.y; e[3] = p2.x;
        e[4] = p1.y; e[5] = p1.x; e[6] = p0.y; e[7] = p0.x;
    }
}

__global__ void __launch_bounds__(256) scan_kernel(float* __restrict__ out) {
    const int sid = blockIdx.x;            // 0..4095
    const int b   = sid >> 9;
    const int rem = sid & 511;
    const int dir = rem >> 8;              // 0 fwd, 1 bwd
    const int ch  = rem & 255;

    const __half* hp = g_fb + ((size_t)b * O_OUT + (size_t)dir * 512 + ch) * L_SEQ;
    const __half* gp = hp + (size_t)256 * L_SEQ;
    float* op = out + ((size_t)b * 512 + (size_t)dir * 256 + ch) * L_SEQ;

    const int tid = threadIdx.x;
    const int lane = tid & 31;
    const int warp = tid >> 5;

    __shared__ float totA[8], totV[8];
    float carryH = 0.f;

    #pragma unroll 1
    for (int s = 0; s < L_SEQ / 2048; ++s) {
        const int base = s * 2048 + tid * 8;
        float h[8], g[8];
        if (dir == 0) {
            load_h8(hp + base, 0, h);
            load_h8(gp + base, 0, g);
        } else {
            int gi = L_SEQ - 8 - base;
            load_h8(hp + gi, 1, h);
            load_h8(gp + gi, 1, g);
        }

        float a[8], v[8];
        #pragma unroll
        for (int i = 0; i < 8; i++) gate(h[i], g[i], a[i], v[i]);

        float A = a[0], V = v[0];
        #pragma unroll
        for (int i = 1; i < 8; i++) { V = fmaf(a[i], V, v[i]); A *= a[i]; }

        #pragma unroll
        for (int off = 1; off < 32; off <<= 1) {
            float Au = __shfl_up_sync(0xffffffffu, A, off);
            float Vu = __shfl_up_sync(0xffffffffu, V, off);
            if (lane >= off) { V = fmaf(A, Vu, V); A *= Au; }
        }
        if (lane == 31) { totA[warp] = A; totV[warp] = V; }
        __syncthreads();

        float Hp = carryH;
        for (int j = 0; j < warp; j++) Hp = fmaf(totA[j], Hp, totV[j]);

        float Ae = __shfl_up_sync(0xffffffffu, A, 1);
        float Ve = __shfl_up_sync(0xffffffffu, V, 1);
        float H = (lane == 0) ? Hp : fmaf(Ae, Hp, Ve);

        float o8[8];
        #pragma unroll
        for (int i = 0; i < 8; i++) { H = fmaf(a[i], H, v[i]); o8[i] = H; }

        if (dir == 0) {
            *(float4*)(op + base)     = make_float4(o8[0], o8[1], o8[2], o8[3]);
            *(float4*)(op + base + 4) = make_float4(o8[4], o8[5], o8[6], o8[7]);
        } else {
            int gi = L_SEQ - 8 - base;
            *(float4*)(op + gi)     = make_float4(o8[7], o8[6], o8[5], o8[4]);
            *(float4*)(op + gi + 4) = make_float4(o8[3], o8[2], o8[1], o8[0]);
        }

        float Hc = carryH;
        #pragma unroll
        for (int j = 0; j < 8; j++) Hc = fmaf(totA[j], Hc, totV[j]);
        carryH = Hc;
        __syncthreads();
    }
}

// ---------------------------------------------------------------------------
extern "C" void kernel_launch(void* const* d_in, const int* in_sizes, int n_in,
                              void* d_out, int out_size) {
    const float* x = (const float*)d_in[0];   // (8, 512, 8192)
    const float* W = (const float*)d_in[1];   // (1024, 512, 1)
    float* out = (float*)d_out;               // (8, 512, 8192)

    // Idempotent, capture-safe (not a stream op); called unconditionally.
    cudaFuncSetAttribute(gemm_f16_kernel,
                         cudaFuncAttributeMaxDynamicSharedMemorySize, SMEM_TOTAL);

    normalize_w_kernel<<<O_OUT, 128>>>(W);

    dim3 grid(O_OUT / GBM, L_SEQ / GBN, BATCH);   // M fastest for x L2 reuse
    gemm_f16_kernel<<<grid, NT, SMEM_TOTAL>>>(x);

    scan_kernel<<<BATCH * 512, 256>>>(out);
}